// round 3
// baseline (speedup 1.0000x reference)
#include <cuda_runtime.h>
#include <math.h>

// ---------------- problem constants ----------------
#define BATCH 128
#define CCH   512
#define SS    121      // 11*11
#define SDIM  11
#define KK    9        // 3*3
#define C2    1024     // 2*C
#define CR    32       // C/SIGMA
#define OUT0  (BATCH*CCH*SS)

typedef unsigned long long u64;

// ---------------- scratch (device globals; no allocation) ----------------
__device__ float g_A1[(size_t)BATCH * C2 * SS];
__device__ float g_asum[C2 * SS];
__device__ float g_acc1[C2 * SS];
__device__ float g_acc2[CCH * SS];
__device__ float g_tmp[C2 * SS];
__device__ float g_task[CCH * SS];
__device__ float g_sk[BATCH * SS * KK];
__device__ float g_skraw[BATCH * SS * KK];
__device__ float g_skt[SS * KK];
__device__ float g_sktraw[SS * KK];
__device__ float g_y[BATCH * CCH];
__device__ float g_yt[CCH];
__device__ float g_ck[(size_t)BATCH * CCH * KK];
__device__ float g_ckt[CCH * KK];

// ---------------- packed f32x2 helpers ----------------
__device__ __forceinline__ u64 ffma2(u64 a, u64 b, u64 c) {
    u64 d;
    asm("fma.rn.f32x2 %0, %1, %2, %3;" : "=l"(d) : "l"(a), "l"(b), "l"(c));
    return d;
}
__device__ __forceinline__ u64 pack2(float v) {
    u64 d;
    asm("mov.b64 %0, {%1, %1};" : "=l"(d) : "f"(v));
    return d;
}
__device__ __forceinline__ float lo32(u64 v) { return __uint_as_float((unsigned)v); }
__device__ __forceinline__ float hi32(u64 v) { return __uint_as_float((unsigned)(v >> 32)); }

// ================= 128x128 tiled SGEMM, FFMA2 inner loop, double-buffered =================
// O[o][p] = act( (sum_c W[o][c]*X[c][p] + bias[o]) * gamma[o]/sqrt(1+eps) + beta[o] )
// mode 0: BN+relu store; mode 1: BN+relu atomicAdd; mode 2: BN+sigmoid store;
// mode 3: raw atomicAdd (split-K partial, no BN)
#define BM 128
#define BN_ 128
#define BK 8

__global__ __launch_bounds__(256, 2) void gemm128(
    const float* __restrict__ W, const float* __restrict__ X,
    const float* __restrict__ bias, const float* __restrict__ gamma,
    const float* __restrict__ beta, float* __restrict__ out,
    int Kd, int P, int kchunk, long long strideX, long long strideO, int mode)
{
    // W tile stored duplicated: Ws2[buf][k][m] = {W[m], W[m]} as b64
    __shared__ __align__(16) u64 Ws2[2][BK][BM + 2];
    __shared__ __align__(16) float Xs[2][BK][BN_];

    const int b = blockIdx.z;
    const float* Xb = X + (long long)b * strideX;
    float* Ob = out + (long long)b * strideO;
    const int row0 = blockIdx.y * BM;
    const int k_begin = blockIdx.x * kchunk;

    const int tid = threadIdx.x;
    const int warp = tid >> 5, lane = tid & 31;
    const int wr = warp & 3, wc = warp >> 2;   // 4x2 warp grid
    const int lr = lane & 3, lc = lane >> 2;   // 4x8 lane grid
    const int tm = wr * 32 + lr * 8;           // thread row base
    const int tn = wc * 64 + lc * 8;           // thread col base

    const int wm = tid >> 1;
    const int wk = (tid & 1) * 4;

    u64 acc[8][4];
#pragma unroll
    for (int i = 0; i < 8; i++)
#pragma unroll
        for (int j = 0; j < 4; j++) acc[i][j] = 0ull;

    const int nt = kchunk / BK;

    // prologue: tile 0 -> buffer 0
    {
        float4 w4 = *(const float4*)&W[(long long)(row0 + wm) * Kd + k_begin + wk];
        Ws2[0][wk + 0][wm] = pack2(w4.x); Ws2[0][wk + 1][wm] = pack2(w4.y);
        Ws2[0][wk + 2][wm] = pack2(w4.z); Ws2[0][wk + 3][wm] = pack2(w4.w);
#pragma unroll
        for (int i = 0; i < 4; i++) {
            int idx = tid + i * 256;
            int kk = idx >> 7, p = idx & 127;
            Xs[0][kk][p] = (p < P) ? Xb[(long long)(k_begin + kk) * P + p] : 0.f;
        }
    }
    __syncthreads();

    for (int t = 0; t < nt; t++) {
        const int cur = t & 1;
        float4 w4;
        float x4[4];
        const bool has_next = (t + 1 < nt);
        if (has_next) {
            int k1 = k_begin + (t + 1) * BK;
            w4 = *(const float4*)&W[(long long)(row0 + wm) * Kd + k1 + wk];
#pragma unroll
            for (int i = 0; i < 4; i++) {
                int idx = tid + i * 256;
                int kk = idx >> 7, p = idx & 127;
                x4[i] = (p < P) ? Xb[(long long)(k1 + kk) * P + p] : 0.f;
            }
        }
#pragma unroll
        for (int kk = 0; kk < BK; kk++) {
            u64 a2[8], b2[4];
            const u64* xu = (const u64*)&Xs[cur][kk][0];
#pragma unroll
            for (int i = 0; i < 8; i++) a2[i] = Ws2[cur][kk][tm + i];
#pragma unroll
            for (int j = 0; j < 4; j++) b2[j] = xu[(tn >> 1) + j];
#pragma unroll
            for (int i = 0; i < 8; i++)
#pragma unroll
                for (int j = 0; j < 4; j++)
                    acc[i][j] = ffma2(a2[i], b2[j], acc[i][j]);
        }
        if (has_next) {
            const int nb = cur ^ 1;
            Ws2[nb][wk + 0][wm] = pack2(w4.x); Ws2[nb][wk + 1][wm] = pack2(w4.y);
            Ws2[nb][wk + 2][wm] = pack2(w4.z); Ws2[nb][wk + 3][wm] = pack2(w4.w);
#pragma unroll
            for (int i = 0; i < 4; i++) {
                int idx = tid + i * 256;
                int kk = idx >> 7, p = idx & 127;
                Xs[nb][kk][p] = x4[i];
            }
            __syncthreads();
        }
    }

    if (mode == 3) {
#pragma unroll
        for (int i = 0; i < 8; i++) {
            int r = row0 + tm + i;
#pragma unroll
            for (int j = 0; j < 4; j++) {
                int p0 = tn + 2 * j;
                if (p0 < P)     atomicAdd(&Ob[(long long)r * P + p0],     lo32(acc[i][j]));
                if (p0 + 1 < P) atomicAdd(&Ob[(long long)r * P + p0 + 1], hi32(acc[i][j]));
            }
        }
    } else {
        const float rs = rsqrtf(1.f + 1e-5f);
#pragma unroll
        for (int i = 0; i < 8; i++) {
            int r = row0 + tm + i;
            float sc = gamma[r] * rs, sh = beta[r], bi = bias[r];
#pragma unroll
            for (int j = 0; j < 4; j++) {
                float v2[2] = {lo32(acc[i][j]), hi32(acc[i][j])};
#pragma unroll
                for (int h = 0; h < 2; h++) {
                    int p = tn + 2 * j + h;
                    if (p < P) {
                        float v = (v2[h] + bi) * sc + sh;
                        if (mode == 0) {
                            Ob[(long long)r * P + p] = fmaxf(v, 0.f);
                        } else if (mode == 1) {
                            atomicAdd(&Ob[(long long)r * P + p], fmaxf(v, 0.f));
                        } else {
                            Ob[(long long)r * P + p] = 1.f / (1.f + expf(-v));
                        }
                    }
                }
            }
        }
    }
}

// ---------------- zero fill ----------------
__global__ void zero_k(float* p, int n) {
    int i = blockIdx.x * 256 + threadIdx.x;
    if (i < n) p[i] = 0.f;
}

// ---------------- split-K epilogue: BN + act (0:relu, 1:sigmoid) ----------------
__global__ void epi_bn(const float* __restrict__ acc, const float* __restrict__ bias,
                       const float* __restrict__ gamma, const float* __restrict__ beta,
                       float* __restrict__ out, int P, int n, int mode)
{
    int i = blockIdx.x * 256 + threadIdx.x;
    if (i < n) {
        int r = i / P;
        float v = (acc[i] + bias[r]) * gamma[r] * rsqrtf(1.f + 1e-5f) + beta[r];
        out[i] = mode ? (1.f / (1.f + expf(-v))) : fmaxf(v, 0.f);
    }
}

// ---------------- spatial kernel, split over channel chunks ----------------
// raw[b][p][kk] += sum_{c in chunk} f[b,c,p]*w_conv[kk,c]
__global__ __launch_bounds__(128) void spatial_part(
    const float* __restrict__ f, const float* __restrict__ w_conv,
    float* __restrict__ raw)
{
    __shared__ float wc[KK * 128];
    const int b = blockIdx.x;
    const int c0 = blockIdx.y * 128;
    const int tid = threadIdx.x;
    for (int i = tid; i < KK * 128; i += 128) {
        int k = i >> 7, cc = i & 127;
        wc[i] = w_conv[k * CCH + c0 + cc];
    }
    __syncthreads();
    if (tid < SS) {
        float acc[KK];
#pragma unroll
        for (int k = 0; k < KK; k++) acc[k] = 0.f;
        const float* fb = f + (long long)b * CCH * SS + (long long)c0 * SS;
        for (int cc = 0; cc < 128; cc++) {
            float xv = fb[cc * SS + tid];
#pragma unroll
            for (int k = 0; k < KK; k++) acc[k] = fmaf(xv, wc[k * 128 + cc], acc[k]);
        }
#pragma unroll
        for (int k = 0; k < KK; k++)
            atomicAdd(&raw[(long long)b * SS * KK + tid * KK + k], acc[k]);
    }
}

// spatial BN epilogue: out[b][p][k] = (raw + b_conv[k]) * g_sp[p]/sqrt(1+eps) + b_sp[p]
__global__ __launch_bounds__(128) void spatial_bn(
    const float* __restrict__ raw, const float* __restrict__ b_conv,
    const float* __restrict__ g_sp, const float* __restrict__ b_sp,
    float* __restrict__ out)
{
    const int b = blockIdx.x;
    const int tid = threadIdx.x;
    if (tid < SS) {
        float gs = g_sp[tid] * rsqrtf(1.f + 1e-5f);
        float bs = b_sp[tid];
#pragma unroll
        for (int k = 0; k < KK; k++) {
            long long idx = (long long)b * SS * KK + tid * KK + k;
            out[idx] = (raw[idx] + b_conv[k]) * gs + bs;
        }
    }
}

// ---------------- DCT pooling ----------------
__global__ __launch_bounds__(128) void dct_pool(
    const float* __restrict__ f, const float* __restrict__ dct, float* __restrict__ y)
{
    const int b = blockIdx.y;
    const int c = blockIdx.x * 4 + (threadIdx.x >> 5);
    const int lane = threadIdx.x & 31;
    const float* fb = f + ((long long)b * CCH + c) * SS;
    const float* dc = dct + (long long)c * SS;
    float s = 0.f;
    for (int p = lane; p < SS; p += 32) s = fmaf(fb[p], dc[p], s);
#pragma unroll
    for (int o = 16; o > 0; o >>= 1) s += __shfl_xor_sync(0xffffffffu, s, o);
    if (lane == 0) y[(long long)b * CCH + c] = s;
}

// ---------------- channel-attention MLP ----------------
__global__ __launch_bounds__(256) void mlp_k(
    const float* __restrict__ y, const float* __restrict__ fc1,
    const float* __restrict__ fc2, const float* __restrict__ g_ch,
    const float* __restrict__ b_ch, float* __restrict__ ck)
{
    __shared__ float ys[CCH];
    __shared__ float hs[CR];
    const int b = blockIdx.x;
    const int tid = threadIdx.x;
    for (int i = tid; i < CCH; i += 256) ys[i] = y[(long long)b * CCH + i];
    __syncthreads();
    if (tid < CR) {
        const float* r = fc1 + tid * CCH;
        float s = 0.f;
        for (int c = 0; c < CCH; c++) s = fmaf(ys[c], r[c], s);
        hs[tid] = fmaxf(s, 0.f);
    }
    __syncthreads();
    const float rs = rsqrtf(1.f + 1e-5f);
    for (int m = tid; m < CCH * KK; m += 256) {
        const float* r = fc2 + m * CR;
        float s = 0.f;
#pragma unroll
        for (int j = 0; j < CR; j++) s = fmaf(hs[j], r[j], s);
        s = 1.f / (1.f + expf(-s));
        int c = m / KK;
        ck[(long long)b * CCH * KK + m] = s * g_ch[c] * rs + b_ch[c];
    }
}

// ---------------- task kernel writer ----------------
__global__ __launch_bounds__(128) void tk_writer(
    const float* __restrict__ skt, const float* __restrict__ ckt, float* __restrict__ tk)
{
    const int c = blockIdx.x;
    for (int i = threadIdx.x; i < SS * KK; i += 128) {
        int kk = i % KK;
        tk[(long long)c * SS * KK + i] = skt[i] * ckt[c * KK + kk];
    }
}

// ---------------- final: adapted + x (8 channels per block) ----------------
__global__ __launch_bounds__(128) void final_k(
    const float* __restrict__ x, const float* __restrict__ sk,
    const float* __restrict__ ck, const float* __restrict__ tk,
    float* __restrict__ out)
{
    __shared__ float xs[13 * 13];
    __shared__ float sks[SS * KK];
    const int c0 = blockIdx.x * 8, b = blockIdx.y;
    const int tid = threadIdx.x;

    for (int i = tid; i < 169; i += 128) xs[i] = 0.f;
    for (int i = tid; i < SS * KK; i += 128) sks[i] = sk[(long long)b * SS * KK + i];
    __syncthreads();

    const int p = tid;
    const int h = p / SDIM, w = p % SDIM;

    for (int cg = 0; cg < 8; cg++) {
        const int c = c0 + cg;
        const float* xb = x + ((long long)b * CCH + c) * SS;
        if (p < SS) xs[(h + 1) * 13 + (w + 1)] = xb[p];
        __syncthreads();
        if (p < SS) {
            float ckv[KK];
#pragma unroll
            for (int k = 0; k < KK; k++) ckv[k] = ck[((long long)b * CCH + c) * KK + k];
            const float* tkc = tk + (long long)c * SS * KK;
            float acc = 0.f;
#pragma unroll
            for (int k = 0; k < KK; k++) {
                int ki = k / 3, kj = k % 3;
                float xv = xs[(h + ki) * 13 + (w + kj)];
                acc = fmaf(xv, tkc[p * KK + k] * sks[p * KK + k] * ckv[k], acc);
            }
            out[((long long)b * CCH + c) * SS + p] = acc * (1.f / 9.f) + xb[p];
        }
        __syncthreads();
    }
}

// ---------------- launch ----------------
extern "C" void kernel_launch(void* const* d_in, const int* in_sizes, int n_in,
                              void* d_out, int out_size)
{
    const float* x      = (const float*)d_in[0];
    const float* dct_w  = (const float*)d_in[1];
    const float* w_conv = (const float*)d_in[2];
    const float* b_conv = (const float*)d_in[3];
    const float* g_sp   = (const float*)d_in[4];
    const float* b_sp   = (const float*)d_in[5];
    const float* g_ch   = (const float*)d_in[6];
    const float* b_ch   = (const float*)d_in[7];
    const float* fc1    = (const float*)d_in[8];
    const float* fc2    = (const float*)d_in[9];
    const float* up_w1  = (const float*)d_in[10];
    const float* up_b1  = (const float*)d_in[11];
    const float* up_g1  = (const float*)d_in[12];
    const float* up_bb1 = (const float*)d_in[13];
    const float* up_w2  = (const float*)d_in[14];
    const float* up_b2  = (const float*)d_in[15];
    const float* up_g2  = (const float*)d_in[16];
    const float* up_bb2 = (const float*)d_in[17];
    const float* lo_w1  = (const float*)d_in[18];
    const float* lo_b1  = (const float*)d_in[19];
    const float* lo_g1  = (const float*)d_in[20];
    const float* lo_bb1 = (const float*)d_in[21];
    const float* lo_w2  = (const float*)d_in[22];
    const float* lo_b2  = (const float*)d_in[23];
    const float* lo_g2  = (const float*)d_in[24];
    const float* lo_bb2 = (const float*)d_in[25];

    float *A1, *asum, *acc1, *acc2, *tmp, *task;
    float *sk, *skraw, *skt, *sktraw, *y, *yt, *ck, *ckt;
    cudaGetSymbolAddress((void**)&A1,     g_A1);
    cudaGetSymbolAddress((void**)&asum,   g_asum);
    cudaGetSymbolAddress((void**)&acc1,   g_acc1);
    cudaGetSymbolAddress((void**)&acc2,   g_acc2);
    cudaGetSymbolAddress((void**)&tmp,    g_tmp);
    cudaGetSymbolAddress((void**)&task,   g_task);
    cudaGetSymbolAddress((void**)&sk,     g_sk);
    cudaGetSymbolAddress((void**)&skraw,  g_skraw);
    cudaGetSymbolAddress((void**)&skt,    g_skt);
    cudaGetSymbolAddress((void**)&sktraw, g_sktraw);
    cudaGetSymbolAddress((void**)&y,      g_y);
    cudaGetSymbolAddress((void**)&yt,     g_yt);
    cudaGetSymbolAddress((void**)&ck,     g_ck);
    cudaGetSymbolAddress((void**)&ckt,    g_ckt);

    float* out = (float*)d_out;
    float* tk  = out + OUT0;

    // zero accumulators
    zero_k<<<(C2 * SS + 255) / 256, 256>>>(asum, C2 * SS);
    zero_k<<<(C2 * SS + 255) / 256, 256>>>(acc1, C2 * SS);
    zero_k<<<(CCH * SS + 255) / 256, 256>>>(acc2, CCH * SS);
    zero_k<<<(BATCH * SS * KK + 255) / 256, 256>>>(skraw, BATCH * SS * KK);
    zero_k<<<(SS * KK + 255) / 256, 256>>>(sktraw, SS * KK);

    // instance-path small kernels
    spatial_part<<<dim3(BATCH, CCH / 128), 128>>>(x, w_conv, skraw);
    spatial_bn<<<BATCH, 128>>>(skraw, b_conv, g_sp, b_sp, sk);
    dct_pool<<<dim3(CCH / 4, BATCH), 128>>>(x, dct_w, y);
    mlp_k<<<BATCH, 256>>>(y, fc1, fc2, g_ch, b_ch, ck);

    // CLM task path
    gemm128<<<dim3(1, C2 / BM, BATCH), 256>>>(up_w1, x, up_b1, up_g1, up_bb1,
        A1, CCH, SS, CCH, (long long)CCH * SS, (long long)C2 * SS, 0);
    gemm128<<<dim3(1, C2 / BM, BATCH), 256>>>(up_w2, A1, up_b2, up_g2, up_bb2,
        asum, C2, SS, C2, (long long)C2 * SS, 0, 1);
    gemm128<<<dim3(16, C2 / BM, 1), 256>>>(lo_w1, asum, lo_b1, lo_g1, lo_bb1,
        acc1, C2, SS, C2 / 16, 0, 0, 3);
    epi_bn<<<(C2 * SS + 255) / 256, 256>>>(acc1, lo_b1, lo_g1, lo_bb1, tmp, SS, C2 * SS, 0);
    gemm128<<<dim3(16, CCH / BM, 1), 256>>>(lo_w2, tmp, lo_b2, lo_g2, lo_bb2,
        acc2, C2, SS, C2 / 16, 0, 0, 3);
    epi_bn<<<(CCH * SS + 255) / 256, 256>>>(acc2, lo_b2, lo_g2, lo_bb2, task, SS, CCH * SS, 1);

    // task-path small kernels
    spatial_part<<<dim3(1, CCH / 128), 128>>>(task, w_conv, sktraw);
    spatial_bn<<<1, 128>>>(sktraw, b_conv, g_sp, b_sp, skt);
    dct_pool<<<dim3(CCH / 4, 1), 128>>>(task, dct_w, yt);
    mlp_k<<<1, 256>>>(yt, fc1, fc2, g_ch, b_ch, ckt);

    // outputs
    tk_writer<<<CCH, 128>>>(skt, ckt, tk);
    final_k<<<dim3(CCH / 8, BATCH), 128>>>(x, sk, ck, tk, out);
}

// round 4
// speedup vs baseline: 1.9836x; 1.9836x over previous
#include <cuda_runtime.h>
#include <math.h>

// ---------------- problem constants ----------------
#define BATCH 128
#define CCH   512
#define SS    121      // 11*11
#define SDIM  11
#define KK    9        // 3*3
#define C2    1024     // 2*C
#define CR    32       // C/SIGMA
#define OUT0  (BATCH*CCH*SS)

// ---------------- scratch (device globals; no allocation) ----------------
__device__ float g_A1[(size_t)BATCH * C2 * SS];
__device__ float g_asum[C2 * SS];
__device__ float g_acc1[C2 * SS];
__device__ float g_acc2[CCH * SS];
__device__ float g_tmp[C2 * SS];
__device__ float g_task[CCH * SS];
__device__ float g_sk[BATCH * SS * KK];
__device__ float g_skraw[BATCH * SS * KK];
__device__ float g_skt[SS * KK];
__device__ float g_sktraw[SS * KK];
__device__ float g_y[BATCH * CCH];
__device__ float g_yt[CCH];
__device__ float g_ck[(size_t)BATCH * CCH * KK];
__device__ float g_ckt[CCH * KK];

// ---------------- tf32 helpers ----------------
__device__ __forceinline__ float tf32_hi(float v) {
    return __uint_as_float(__float_as_uint(v) & 0xFFFFE000u);
}
__device__ __forceinline__ void mma_tf32(float c[4], const float a[4], const float b[2]) {
    asm volatile(
        "mma.sync.aligned.m16n8k8.row.col.f32.tf32.tf32.f32 "
        "{%0,%1,%2,%3}, {%4,%5,%6,%7}, {%8,%9}, {%0,%1,%2,%3};"
        : "+f"(c[0]), "+f"(c[1]), "+f"(c[2]), "+f"(c[3])
        : "r"(__float_as_uint(a[0])), "r"(__float_as_uint(a[1])),
          "r"(__float_as_uint(a[2])), "r"(__float_as_uint(a[3])),
          "r"(__float_as_uint(b[0])), "r"(__float_as_uint(b[1])));
}

// ================= tensor-core GEMM (3xTF32), 128x128 tile, BK=8 =================
// O[o][p] = act( (sum_c W[o][c]*X[c][p] + bias[o]) * gamma[o]/sqrt(1+eps) + beta[o] )
// mode 0: BN+relu store; mode 1: BN+relu atomicAdd; mode 2: BN+sigmoid; mode 3: raw atomicAdd
#define BM 128
#define MT 8      // m16 tiles per block
#define NT 16     // n8 tiles per block

__global__ __launch_bounds__(256) void tgemm(
    const float* __restrict__ W, const float* __restrict__ X,
    const float* __restrict__ bias, const float* __restrict__ gamma,
    const float* __restrict__ beta, float* __restrict__ out,
    int Kd, int P, int kchunk, long long strideX, long long strideO, int mode)
{
    // fragment-major smem: each lane's frag elems contiguous
    __shared__ __align__(16) float Asm[2][2][MT][32][4];  // [buf][hi/lo][mt][lane][a0..a3]
    __shared__ __align__(16) float Bsm[2][2][NT][32][2];  // [buf][hi/lo][nt][lane][b0..b1]

    const int bz = blockIdx.z;
    const float* Xb = X + (long long)bz * strideX;
    float* Ob = out + (long long)bz * strideO;
    const int row0 = blockIdx.y * BM;
    const int k_begin = blockIdx.x * kchunk;

    const int tid = threadIdx.x, lane = tid & 31, warp = tid >> 5;
    const int g = lane >> 2, tg = lane & 3;

    // loader roles: A: mt = warp; B: nt = warp*2 + {0,1}
    // compute roles: warp grid 2(m) x 4(n); warp tile 64x32
    const int wm = warp >> 2;   // 0..1
    const int wn = warp & 3;    // 0..3

    float acc[4][4][4];
#pragma unroll
    for (int i = 0; i < 4; i++)
#pragma unroll
        for (int j = 0; j < 4; j++)
#pragma unroll
            for (int e = 0; e < 4; e++) acc[i][j][e] = 0.f;

    const int nt_iters = kchunk / 8;

    // ---- stage 0 ----
    {
        const int k = k_begin;
        // A fragments: rows (g, g+8), cols (tg, tg+4) of this mt tile
        const float* wr = W + (long long)(row0 + warp * 16 + g) * Kd + k + tg;
        float v00 = wr[0], v01 = wr[4];
        float v10 = wr[8 * Kd], v11 = wr[8 * Kd + 4];
        float h0 = tf32_hi(v00), h1 = tf32_hi(v10), h2 = tf32_hi(v01), h3 = tf32_hi(v11);
        Asm[0][0][warp][lane][0] = h0;        Asm[0][0][warp][lane][1] = h1;
        Asm[0][0][warp][lane][2] = h2;        Asm[0][0][warp][lane][3] = h3;
        Asm[0][1][warp][lane][0] = v00 - h0;  Asm[0][1][warp][lane][1] = v10 - h1;
        Asm[0][1][warp][lane][2] = v01 - h2;  Asm[0][1][warp][lane][3] = v11 - h3;
#pragma unroll
        for (int q = 0; q < 2; q++) {
            int nt = warp * 2 + q;
            int p = nt * 8 + g;
            float v0 = 0.f, v1 = 0.f;
            if (p < P) {
                v0 = Xb[(long long)(k + tg) * P + p];
                v1 = Xb[(long long)(k + tg + 4) * P + p];
            }
            float b0 = tf32_hi(v0), b1 = tf32_hi(v1);
            Bsm[0][0][nt][lane][0] = b0;       Bsm[0][0][nt][lane][1] = b1;
            Bsm[0][1][nt][lane][0] = v0 - b0;  Bsm[0][1][nt][lane][1] = v1 - b1;
        }
    }
    __syncthreads();

    for (int t = 0; t < nt_iters; t++) {
        const int cur = t & 1;
        const bool has_next = (t + 1 < nt_iters);
        // prefetch next tile to registers
        float v00, v01, v10, v11, x0[2], x1[2];
        if (has_next) {
            const int k = k_begin + (t + 1) * 8;
            const float* wr = W + (long long)(row0 + warp * 16 + g) * Kd + k + tg;
            v00 = wr[0]; v01 = wr[4];
            v10 = wr[8 * Kd]; v11 = wr[8 * Kd + 4];
#pragma unroll
            for (int q = 0; q < 2; q++) {
                int nt = warp * 2 + q;
                int p = nt * 8 + g;
                x0[q] = 0.f; x1[q] = 0.f;
                if (p < P) {
                    x0[q] = Xb[(long long)(k + tg) * P + p];
                    x1[q] = Xb[(long long)(k + tg + 4) * P + p];
                }
            }
        }

        // load fragments (hi and lo)
        float aF[2][4][4], bF[2][4][2];
#pragma unroll
        for (int s = 0; s < 2; s++)
#pragma unroll
            for (int i = 0; i < 4; i++) {
                float4 a4 = *(const float4*)&Asm[cur][s][wm * 4 + i][lane][0];
                aF[s][i][0] = a4.x; aF[s][i][1] = a4.y; aF[s][i][2] = a4.z; aF[s][i][3] = a4.w;
            }
#pragma unroll
        for (int s = 0; s < 2; s++)
#pragma unroll
            for (int j = 0; j < 4; j++) {
                float2 b2 = *(const float2*)&Bsm[cur][s][wn * 4 + j][lane][0];
                bF[s][j][0] = b2.x; bF[s][j][1] = b2.y;
            }

        // 3xTF32: hi*hi + hi*lo + lo*hi
#pragma unroll
        for (int i = 0; i < 4; i++)
#pragma unroll
            for (int j = 0; j < 4; j++) {
                mma_tf32(acc[i][j], aF[0][i], bF[0][j]);
                mma_tf32(acc[i][j], aF[0][i], bF[1][j]);
                mma_tf32(acc[i][j], aF[1][i], bF[0][j]);
            }

        if (has_next) {
            const int nb = cur ^ 1;
            float h0 = tf32_hi(v00), h1 = tf32_hi(v10), h2 = tf32_hi(v01), h3 = tf32_hi(v11);
            Asm[nb][0][warp][lane][0] = h0;        Asm[nb][0][warp][lane][1] = h1;
            Asm[nb][0][warp][lane][2] = h2;        Asm[nb][0][warp][lane][3] = h3;
            Asm[nb][1][warp][lane][0] = v00 - h0;  Asm[nb][1][warp][lane][1] = v10 - h1;
            Asm[nb][1][warp][lane][2] = v01 - h2;  Asm[nb][1][warp][lane][3] = v11 - h3;
#pragma unroll
            for (int q = 0; q < 2; q++) {
                int nt = warp * 2 + q;
                float b0 = tf32_hi(x0[q]), b1 = tf32_hi(x1[q]);
                Bsm[nb][0][nt][lane][0] = b0;          Bsm[nb][0][nt][lane][1] = b1;
                Bsm[nb][1][nt][lane][0] = x0[q] - b0;  Bsm[nb][1][nt][lane][1] = x1[q] - b1;
            }
            __syncthreads();
        }
    }

    // ---- epilogue ----
    const float rsc = rsqrtf(1.f + 1e-5f);
#pragma unroll
    for (int i = 0; i < 4; i++) {
        int r0 = row0 + (wm * 4 + i) * 16 + g;
#pragma unroll
        for (int half = 0; half < 2; half++) {
            int r = r0 + half * 8;
            float sc = 0.f, sh = 0.f, bi = 0.f;
            if (mode != 3) { sc = gamma[r] * rsc; sh = beta[r]; bi = bias[r]; }
#pragma unroll
            for (int j = 0; j < 4; j++) {
                int p0 = (wn * 4 + j) * 8 + 2 * tg;
#pragma unroll
                for (int e = 0; e < 2; e++) {
                    int p = p0 + e;
                    if (p < P) {
                        float raw = acc[i][j][half * 2 + e];
                        if (mode == 3) {
                            atomicAdd(&Ob[(long long)r * P + p], raw);
                        } else {
                            float v = (raw + bi) * sc + sh;
                            if (mode == 0)      Ob[(long long)r * P + p] = fmaxf(v, 0.f);
                            else if (mode == 1) atomicAdd(&Ob[(long long)r * P + p], fmaxf(v, 0.f));
                            else                Ob[(long long)r * P + p] = 1.f / (1.f + expf(-v));
                        }
                    }
                }
            }
        }
    }
}

// ---------------- zero fill ----------------
__global__ void zero_k(float* p, int n) {
    int i = blockIdx.x * 256 + threadIdx.x;
    if (i < n) p[i] = 0.f;
}

// ---------------- split-K epilogue: BN + act (0:relu, 1:sigmoid) ----------------
__global__ void epi_bn(const float* __restrict__ acc, const float* __restrict__ bias,
                       const float* __restrict__ gamma, const float* __restrict__ beta,
                       float* __restrict__ out, int P, int n, int mode)
{
    int i = blockIdx.x * 256 + threadIdx.x;
    if (i < n) {
        int r = i / P;
        float v = (acc[i] + bias[r]) * gamma[r] * rsqrtf(1.f + 1e-5f) + beta[r];
        out[i] = mode ? (1.f / (1.f + expf(-v))) : fmaxf(v, 0.f);
    }
}

// ---------------- spatial kernel, split over channel chunks ----------------
__global__ __launch_bounds__(128) void spatial_part(
    const float* __restrict__ f, const float* __restrict__ w_conv,
    float* __restrict__ raw)
{
    __shared__ float wc[KK * 128];
    const int b = blockIdx.x;
    const int c0 = blockIdx.y * 128;
    const int tid = threadIdx.x;
    for (int i = tid; i < KK * 128; i += 128) {
        int k = i >> 7, cc = i & 127;
        wc[i] = w_conv[k * CCH + c0 + cc];
    }
    __syncthreads();
    if (tid < SS) {
        float acc[KK];
#pragma unroll
        for (int k = 0; k < KK; k++) acc[k] = 0.f;
        const float* fb = f + (long long)b * CCH * SS + (long long)c0 * SS;
        for (int cc = 0; cc < 128; cc++) {
            float xv = fb[cc * SS + tid];
#pragma unroll
            for (int k = 0; k < KK; k++) acc[k] = fmaf(xv, wc[k * 128 + cc], acc[k]);
        }
#pragma unroll
        for (int k = 0; k < KK; k++)
            atomicAdd(&raw[(long long)b * SS * KK + tid * KK + k], acc[k]);
    }
}

__global__ __launch_bounds__(128) void spatial_bn(
    const float* __restrict__ raw, const float* __restrict__ b_conv,
    const float* __restrict__ g_sp, const float* __restrict__ b_sp,
    float* __restrict__ out)
{
    const int b = blockIdx.x;
    const int tid = threadIdx.x;
    if (tid < SS) {
        float gs = g_sp[tid] * rsqrtf(1.f + 1e-5f);
        float bs = b_sp[tid];
#pragma unroll
        for (int k = 0; k < KK; k++) {
            long long idx = (long long)b * SS * KK + tid * KK + k;
            out[idx] = (raw[idx] + b_conv[k]) * gs + bs;
        }
    }
}

// ---------------- DCT pooling ----------------
__global__ __launch_bounds__(128) void dct_pool(
    const float* __restrict__ f, const float* __restrict__ dct, float* __restrict__ y)
{
    const int b = blockIdx.y;
    const int c = blockIdx.x * 4 + (threadIdx.x >> 5);
    const int lane = threadIdx.x & 31;
    const float* fb = f + ((long long)b * CCH + c) * SS;
    const float* dc = dct + (long long)c * SS;
    float s = 0.f;
    for (int p = lane; p < SS; p += 32) s = fmaf(fb[p], dc[p], s);
#pragma unroll
    for (int o = 16; o > 0; o >>= 1) s += __shfl_xor_sync(0xffffffffu, s, o);
    if (lane == 0) y[(long long)b * CCH + c] = s;
}

// ---------------- channel-attention MLP ----------------
__global__ __launch_bounds__(256) void mlp_k(
    const float* __restrict__ y, const float* __restrict__ fc1,
    const float* __restrict__ fc2, const float* __restrict__ g_ch,
    const float* __restrict__ b_ch, float* __restrict__ ck)
{
    __shared__ float ys[CCH];
    __shared__ float hs[CR];
    const int b = blockIdx.x;
    const int tid = threadIdx.x;
    for (int i = tid; i < CCH; i += 256) ys[i] = y[(long long)b * CCH + i];
    __syncthreads();
    if (tid < CR) {
        const float* r = fc1 + tid * CCH;
        float s = 0.f;
        for (int c = 0; c < CCH; c++) s = fmaf(ys[c], r[c], s);
        hs[tid] = fmaxf(s, 0.f);
    }
    __syncthreads();
    const float rs = rsqrtf(1.f + 1e-5f);
    for (int m = tid; m < CCH * KK; m += 256) {
        const float* r = fc2 + m * CR;
        float s = 0.f;
#pragma unroll
        for (int j = 0; j < CR; j++) s = fmaf(hs[j], r[j], s);
        s = 1.f / (1.f + expf(-s));
        int c = m / KK;
        ck[(long long)b * CCH * KK + m] = s * g_ch[c] * rs + b_ch[c];
    }
}

// ---------------- task kernel writer ----------------
__global__ __launch_bounds__(128) void tk_writer(
    const float* __restrict__ skt, const float* __restrict__ ckt, float* __restrict__ tk)
{
    const int c = blockIdx.x;
    for (int i = threadIdx.x; i < SS * KK; i += 128) {
        int kk = i % KK;
        tk[(long long)c * SS * KK + i] = skt[i] * ckt[c * KK + kk];
    }
}

// ---------------- final: adapted + x (8 channels per block) ----------------
__global__ __launch_bounds__(128) void final_k(
    const float* __restrict__ x, const float* __restrict__ sk,
    const float* __restrict__ ck, const float* __restrict__ tk,
    float* __restrict__ out)
{
    __shared__ float xs[13 * 13];
    __shared__ float sks[SS * KK];
    const int c0 = blockIdx.x * 8, b = blockIdx.y;
    const int tid = threadIdx.x;

    for (int i = tid; i < 169; i += 128) xs[i] = 0.f;
    for (int i = tid; i < SS * KK; i += 128) sks[i] = sk[(long long)b * SS * KK + i];
    __syncthreads();

    const int p = tid;
    const int h = p / SDIM, w = p % SDIM;

    for (int cg = 0; cg < 8; cg++) {
        const int c = c0 + cg;
        const float* xb = x + ((long long)b * CCH + c) * SS;
        if (p < SS) xs[(h + 1) * 13 + (w + 1)] = xb[p];
        __syncthreads();
        if (p < SS) {
            float ckv[KK];
#pragma unroll
            for (int k = 0; k < KK; k++) ckv[k] = ck[((long long)b * CCH + c) * KK + k];
            const float* tkc = tk + (long long)c * SS * KK;
            float acc = 0.f;
#pragma unroll
            for (int k = 0; k < KK; k++) {
                int ki = k / 3, kj = k % 3;
                float xv = xs[(h + ki) * 13 + (w + kj)];
                acc = fmaf(xv, tkc[p * KK + k] * sks[p * KK + k] * ckv[k], acc);
            }
            out[((long long)b * CCH + c) * SS + p] = acc * (1.f / 9.f) + xb[p];
        }
        __syncthreads();
    }
}

// ---------------- launch ----------------
extern "C" void kernel_launch(void* const* d_in, const int* in_sizes, int n_in,
                              void* d_out, int out_size)
{
    const float* x      = (const float*)d_in[0];
    const float* dct_w  = (const float*)d_in[1];
    const float* w_conv = (const float*)d_in[2];
    const float* b_conv = (const float*)d_in[3];
    const float* g_sp   = (const float*)d_in[4];
    const float* b_sp   = (const float*)d_in[5];
    const float* g_ch   = (const float*)d_in[6];
    const float* b_ch   = (const float*)d_in[7];
    const float* fc1    = (const float*)d_in[8];
    const float* fc2    = (const float*)d_in[9];
    const float* up_w1  = (const float*)d_in[10];
    const float* up_b1  = (const float*)d_in[11];
    const float* up_g1  = (const float*)d_in[12];
    const float* up_bb1 = (const float*)d_in[13];
    const float* up_w2  = (const float*)d_in[14];
    const float* up_b2  = (const float*)d_in[15];
    const float* up_g2  = (const float*)d_in[16];
    const float* up_bb2 = (const float*)d_in[17];
    const float* lo_w1  = (const float*)d_in[18];
    const float* lo_b1  = (const float*)d_in[19];
    const float* lo_g1  = (const float*)d_in[20];
    const float* lo_bb1 = (const float*)d_in[21];
    const float* lo_w2  = (const float*)d_in[22];
    const float* lo_b2  = (const float*)d_in[23];
    const float* lo_g2  = (const float*)d_in[24];
    const float* lo_bb2 = (const float*)d_in[25];

    float *A1, *asum, *acc1, *acc2, *tmp, *task;
    float *sk, *skraw, *skt, *sktraw, *y, *yt, *ck, *ckt;
    cudaGetSymbolAddress((void**)&A1,     g_A1);
    cudaGetSymbolAddress((void**)&asum,   g_asum);
    cudaGetSymbolAddress((void**)&acc1,   g_acc1);
    cudaGetSymbolAddress((void**)&acc2,   g_acc2);
    cudaGetSymbolAddress((void**)&tmp,    g_tmp);
    cudaGetSymbolAddress((void**)&task,   g_task);
    cudaGetSymbolAddress((void**)&sk,     g_sk);
    cudaGetSymbolAddress((void**)&skraw,  g_skraw);
    cudaGetSymbolAddress((void**)&skt,    g_skt);
    cudaGetSymbolAddress((void**)&sktraw, g_sktraw);
    cudaGetSymbolAddress((void**)&y,      g_y);
    cudaGetSymbolAddress((void**)&yt,     g_yt);
    cudaGetSymbolAddress((void**)&ck,     g_ck);
    cudaGetSymbolAddress((void**)&ckt,    g_ckt);

    float* out = (float*)d_out;
    float* tk  = out + OUT0;

    // zero accumulators
    zero_k<<<(C2 * SS + 255) / 256, 256>>>(asum, C2 * SS);
    zero_k<<<(C2 * SS + 255) / 256, 256>>>(acc1, C2 * SS);
    zero_k<<<(CCH * SS + 255) / 256, 256>>>(acc2, CCH * SS);
    zero_k<<<(BATCH * SS * KK + 255) / 256, 256>>>(skraw, BATCH * SS * KK);
    zero_k<<<(SS * KK + 255) / 256, 256>>>(sktraw, SS * KK);

    // instance-path small kernels
    spatial_part<<<dim3(BATCH, CCH / 128), 128>>>(x, w_conv, skraw);
    spatial_bn<<<BATCH, 128>>>(skraw, b_conv, g_sp, b_sp, sk);
    dct_pool<<<dim3(CCH / 4, BATCH), 128>>>(x, dct_w, y);
    mlp_k<<<BATCH, 256>>>(y, fc1, fc2, g_ch, b_ch, ck);

    // CLM task path (tensor-core GEMMs)
    tgemm<<<dim3(1, C2 / BM, BATCH), 256>>>(up_w1, x, up_b1, up_g1, up_bb1,
        A1, CCH, SS, CCH, (long long)CCH * SS, (long long)C2 * SS, 0);
    tgemm<<<dim3(1, C2 / BM, BATCH), 256>>>(up_w2, A1, up_b2, up_g2, up_bb2,
        asum, C2, SS, C2, (long long)C2 * SS, 0, 1);
    tgemm<<<dim3(16, C2 / BM, 1), 256>>>(lo_w1, asum, lo_b1, lo_g1, lo_bb1,
        acc1, C2, SS, C2 / 16, 0, 0, 3);
    epi_bn<<<(C2 * SS + 255) / 256, 256>>>(acc1, lo_b1, lo_g1, lo_bb1, tmp, SS, C2 * SS, 0);
    tgemm<<<dim3(16, CCH / BM, 1), 256>>>(lo_w2, tmp, lo_b2, lo_g2, lo_bb2,
        acc2, C2, SS, C2 / 16, 0, 0, 3);
    epi_bn<<<(CCH * SS + 255) / 256, 256>>>(acc2, lo_b2, lo_g2, lo_bb2, task, SS, CCH * SS, 1);

    // task-path small kernels
    spatial_part<<<dim3(1, CCH / 128), 128>>>(task, w_conv, sktraw);
    spatial_bn<<<1, 128>>>(sktraw, b_conv, g_sp, b_sp, skt);
    dct_pool<<<dim3(CCH / 4, 1), 128>>>(task, dct_w, yt);
    mlp_k<<<1, 256>>>(yt, fc1, fc2, g_ch, b_ch, ckt);

    // outputs
    tk_writer<<<CCH, 128>>>(skt, ckt, tk);
    final_k<<<dim3(CCH / 8, BATCH), 128>>>(x, sk, ck, tk, out);
}

// round 5
// speedup vs baseline: 2.7610x; 1.3920x over previous
#include <cuda_runtime.h>
#include <cuda_bf16.h>
#include <math.h>

// ---------------- problem constants ----------------
#define BATCH 128
#define CCH   512
#define SS    121      // 11*11
#define SDIM  11
#define KK    9        // 3*3
#define C2    1024     // 2*C
#define CR    32       // C/SIGMA
#define OUT0  (BATCH*CCH*SS)

// ---------------- scratch (device globals; no allocation) ----------------
__device__ float g_A1[(size_t)BATCH * C2 * SS];
__device__ float g_asum[C2 * SS];
__device__ float g_acc1[C2 * SS];
__device__ float g_acc2[CCH * SS];
__device__ float g_tmp[C2 * SS];
__device__ float g_task[CCH * SS];
__device__ float g_sk[BATCH * SS * KK];
__device__ float g_skraw[BATCH * SS * KK];
__device__ float g_skt[SS * KK];
__device__ float g_sktraw[SS * KK];
__device__ float g_y[BATCH * CCH];
__device__ float g_yt[CCH];
__device__ float g_ck[(size_t)BATCH * CCH * KK];
__device__ float g_ckt[CCH * KK];

// ---------------- bf16 split helpers ----------------
// v = hi + lo with hi,lo bf16: covers ~16 mantissa bits
__device__ __forceinline__ void split_pack(float a, float b, unsigned& hi, unsigned& lo) {
    __nv_bfloat162 h = __float22bfloat162_rn(make_float2(a, b));
    float ra = a - __bfloat162float(h.x);
    float rb = b - __bfloat162float(h.y);
    __nv_bfloat162 l = __float22bfloat162_rn(make_float2(ra, rb));
    hi = *(unsigned*)&h;
    lo = *(unsigned*)&l;
}

__device__ __forceinline__ void mma_bf16(float c[4], const unsigned a[4], const unsigned b[2]) {
    asm volatile(
        "mma.sync.aligned.m16n8k16.row.col.f32.bf16.bf16.f32 "
        "{%0,%1,%2,%3}, {%4,%5,%6,%7}, {%8,%9}, {%0,%1,%2,%3};"
        : "+f"(c[0]), "+f"(c[1]), "+f"(c[2]), "+f"(c[3])
        : "r"(a[0]), "r"(a[1]), "r"(a[2]), "r"(a[3]), "r"(b[0]), "r"(b[1]));
}

// ================= tensor-core GEMM (3xBF16 split), 128x128 tile, BK=16 =================
// O[o][p] = act( (sum_c W[o][c]*X[c][p] + bias[o]) * gamma[o]/sqrt(1+eps) + beta[o] )
// mode 0: BN+relu store; mode 1: BN+relu atomicAdd; mode 2: BN+sigmoid; mode 3: raw atomicAdd
#define BM 128
#define MT 8      // m16 tiles per block
#define NT 16     // n8 tiles per block

__global__ __launch_bounds__(256) void tgemm(
    const float* __restrict__ W, const float* __restrict__ X,
    const float* __restrict__ bias, const float* __restrict__ gamma,
    const float* __restrict__ beta, float* __restrict__ out,
    int Kd, int P, int kchunk, long long strideX, long long strideO, int mode)
{
    // fragment-major smem (packed bf16x2 words): [buf][hi/lo][tile][lane][reg]
    __shared__ __align__(16) unsigned Asm[2][2][MT][32][4];
    __shared__ __align__(16) unsigned Bsm[2][2][NT][32][2];

    const int bz = blockIdx.z;
    const float* Xb = X + (long long)bz * strideX;
    float* Ob = out + (long long)bz * strideO;
    const int row0 = blockIdx.y * BM;
    const int k_begin = blockIdx.x * kchunk;

    const int tid = threadIdx.x, lane = tid & 31, warp = tid >> 5;
    const int g = lane >> 2, tg = lane & 3;

    // loader roles: A: mt = warp; B: nt = warp*2 + {0,1}
    // compute roles: warp grid 2(m) x 4(n); warp tile 64x32
    const int wm = warp >> 2;   // 0..1
    const int wn = warp & 3;    // 0..3

    float acc[4][4][4];
#pragma unroll
    for (int i = 0; i < 4; i++)
#pragma unroll
        for (int j = 0; j < 4; j++)
#pragma unroll
            for (int e = 0; e < 4; e++) acc[i][j][e] = 0.f;

    const int nt_iters = kchunk / 16;

    // ---- stage 0 ----
    {
        const int k = k_begin;
        const float* wr = W + (long long)(row0 + warp * 16 + g) * Kd + k + 2 * tg;
        float2 v00 = *(const float2*)wr;              // row g,   k+2tg
        float2 v10 = *(const float2*)(wr + 8 * Kd);   // row g+8, k+2tg
        float2 v01 = *(const float2*)(wr + 8);        // row g,   k+2tg+8
        float2 v11 = *(const float2*)(wr + 8 * Kd + 8);
        unsigned h, l;
        split_pack(v00.x, v00.y, h, l); Asm[0][0][warp][lane][0] = h; Asm[0][1][warp][lane][0] = l;
        split_pack(v10.x, v10.y, h, l); Asm[0][0][warp][lane][1] = h; Asm[0][1][warp][lane][1] = l;
        split_pack(v01.x, v01.y, h, l); Asm[0][0][warp][lane][2] = h; Asm[0][1][warp][lane][2] = l;
        split_pack(v11.x, v11.y, h, l); Asm[0][0][warp][lane][3] = h; Asm[0][1][warp][lane][3] = l;
#pragma unroll
        for (int q = 0; q < 2; q++) {
            int nt = warp * 2 + q;
            int p = nt * 8 + g;
            float b0a = 0.f, b0b = 0.f, b1a = 0.f, b1b = 0.f;
            if (p < P) {
                b0a = Xb[(long long)(k + 2 * tg) * P + p];
                b0b = Xb[(long long)(k + 2 * tg + 1) * P + p];
                b1a = Xb[(long long)(k + 2 * tg + 8) * P + p];
                b1b = Xb[(long long)(k + 2 * tg + 9) * P + p];
            }
            split_pack(b0a, b0b, h, l); Bsm[0][0][nt][lane][0] = h; Bsm[0][1][nt][lane][0] = l;
            split_pack(b1a, b1b, h, l); Bsm[0][0][nt][lane][1] = h; Bsm[0][1][nt][lane][1] = l;
        }
    }
    __syncthreads();

    for (int t = 0; t < nt_iters; t++) {
        const int cur = t & 1;
        const bool has_next = (t + 1 < nt_iters);
        // prefetch next tile to registers
        float2 v00, v01, v10, v11;
        float xb0[2][2], xb1[2][2];
        if (has_next) {
            const int k = k_begin + (t + 1) * 16;
            const float* wr = W + (long long)(row0 + warp * 16 + g) * Kd + k + 2 * tg;
            v00 = *(const float2*)wr;
            v10 = *(const float2*)(wr + 8 * Kd);
            v01 = *(const float2*)(wr + 8);
            v11 = *(const float2*)(wr + 8 * Kd + 8);
#pragma unroll
            for (int q = 0; q < 2; q++) {
                int nt = warp * 2 + q;
                int p = nt * 8 + g;
                xb0[q][0] = 0.f; xb0[q][1] = 0.f; xb1[q][0] = 0.f; xb1[q][1] = 0.f;
                if (p < P) {
                    xb0[q][0] = Xb[(long long)(k + 2 * tg) * P + p];
                    xb0[q][1] = Xb[(long long)(k + 2 * tg + 1) * P + p];
                    xb1[q][0] = Xb[(long long)(k + 2 * tg + 8) * P + p];
                    xb1[q][1] = Xb[(long long)(k + 2 * tg + 9) * P + p];
                }
            }
        }

        // load fragments (hi and lo)
        unsigned aF[2][4][4], bF[2][4][2];
#pragma unroll
        for (int s = 0; s < 2; s++)
#pragma unroll
            for (int i = 0; i < 4; i++) {
                uint4 a4 = *(const uint4*)&Asm[cur][s][wm * 4 + i][lane][0];
                aF[s][i][0] = a4.x; aF[s][i][1] = a4.y; aF[s][i][2] = a4.z; aF[s][i][3] = a4.w;
            }
#pragma unroll
        for (int s = 0; s < 2; s++)
#pragma unroll
            for (int j = 0; j < 4; j++) {
                uint2 b2 = *(const uint2*)&Bsm[cur][s][wn * 4 + j][lane][0];
                bF[s][j][0] = b2.x; bF[s][j][1] = b2.y;
            }

        // 3x split: hi*hi + hi*lo + lo*hi
#pragma unroll
        for (int i = 0; i < 4; i++)
#pragma unroll
            for (int j = 0; j < 4; j++) {
                mma_bf16(acc[i][j], aF[0][i], bF[0][j]);
                mma_bf16(acc[i][j], aF[0][i], bF[1][j]);
                mma_bf16(acc[i][j], aF[1][i], bF[0][j]);
            }

        if (has_next) {
            const int nb = cur ^ 1;
            unsigned h, l;
            split_pack(v00.x, v00.y, h, l); Asm[nb][0][warp][lane][0] = h; Asm[nb][1][warp][lane][0] = l;
            split_pack(v10.x, v10.y, h, l); Asm[nb][0][warp][lane][1] = h; Asm[nb][1][warp][lane][1] = l;
            split_pack(v01.x, v01.y, h, l); Asm[nb][0][warp][lane][2] = h; Asm[nb][1][warp][lane][2] = l;
            split_pack(v11.x, v11.y, h, l); Asm[nb][0][warp][lane][3] = h; Asm[nb][1][warp][lane][3] = l;
#pragma unroll
            for (int q = 0; q < 2; q++) {
                int nt = warp * 2 + q;
                split_pack(xb0[q][0], xb0[q][1], h, l);
                Bsm[nb][0][nt][lane][0] = h; Bsm[nb][1][nt][lane][0] = l;
                split_pack(xb1[q][0], xb1[q][1], h, l);
                Bsm[nb][0][nt][lane][1] = h; Bsm[nb][1][nt][lane][1] = l;
            }
            __syncthreads();
        }
    }

    // ---- epilogue ----
    const float rsc = rsqrtf(1.f + 1e-5f);
#pragma unroll
    for (int i = 0; i < 4; i++) {
        int r0 = row0 + (wm * 4 + i) * 16 + g;
#pragma unroll
        for (int half = 0; half < 2; half++) {
            int r = r0 + half * 8;
            float sc = 0.f, sh = 0.f, bi = 0.f;
            if (mode != 3) { sc = gamma[r] * rsc; sh = beta[r]; bi = bias[r]; }
#pragma unroll
            for (int j = 0; j < 4; j++) {
                int p0 = (wn * 4 + j) * 8 + 2 * tg;
#pragma unroll
                for (int e = 0; e < 2; e++) {
                    int p = p0 + e;
                    if (p < P) {
                        float raw = acc[i][j][half * 2 + e];
                        if (mode == 3) {
                            atomicAdd(&Ob[(long long)r * P + p], raw);
                        } else {
                            float v = (raw + bi) * sc + sh;
                            if (mode == 0)      Ob[(long long)r * P + p] = fmaxf(v, 0.f);
                            else if (mode == 1) atomicAdd(&Ob[(long long)r * P + p], fmaxf(v, 0.f));
                            else                Ob[(long long)r * P + p] = 1.f / (1.f + expf(-v));
                        }
                    }
                }
            }
        }
    }
}

// ---------------- fused zero fill (5 regions in one launch) ----------------
__global__ void zero_multi(float* p0, int n0, float* p1, int n1, float* p2, int n2,
                           float* p3, int n3, float* p4, int n4)
{
    int i = blockIdx.x * 256 + threadIdx.x;
    if (i < n0) { p0[i] = 0.f; return; }
    i -= n0;
    if (i < n1) { p1[i] = 0.f; return; }
    i -= n1;
    if (i < n2) { p2[i] = 0.f; return; }
    i -= n2;
    if (i < n3) { p3[i] = 0.f; return; }
    i -= n3;
    if (i < n4) p4[i] = 0.f;
}

// ---------------- split-K epilogue: BN + act (0:relu, 1:sigmoid) ----------------
__global__ void epi_bn(const float* __restrict__ acc, const float* __restrict__ bias,
                       const float* __restrict__ gamma, const float* __restrict__ beta,
                       float* __restrict__ out, int P, int n, int mode)
{
    int i = blockIdx.x * 256 + threadIdx.x;
    if (i < n) {
        int r = i / P;
        float v = (acc[i] + bias[r]) * gamma[r] * rsqrtf(1.f + 1e-5f) + beta[r];
        out[i] = mode ? (1.f / (1.f + expf(-v))) : fmaxf(v, 0.f);
    }
}

// ---------------- spatial kernel, split over channel chunks ----------------
__global__ __launch_bounds__(128) void spatial_part(
    const float* __restrict__ f, const float* __restrict__ w_conv,
    float* __restrict__ raw)
{
    __shared__ float wc[KK * 128];
    const int b = blockIdx.x;
    const int c0 = blockIdx.y * 128;
    const int tid = threadIdx.x;
    for (int i = tid; i < KK * 128; i += 128) {
        int k = i >> 7, cc = i & 127;
        wc[i] = w_conv[k * CCH + c0 + cc];
    }
    __syncthreads();
    if (tid < SS) {
        float acc[KK];
#pragma unroll
        for (int k = 0; k < KK; k++) acc[k] = 0.f;
        const float* fb = f + (long long)b * CCH * SS + (long long)c0 * SS;
        for (int cc = 0; cc < 128; cc++) {
            float xv = fb[cc * SS + tid];
#pragma unroll
            for (int k = 0; k < KK; k++) acc[k] = fmaf(xv, wc[k * 128 + cc], acc[k]);
        }
#pragma unroll
        for (int k = 0; k < KK; k++)
            atomicAdd(&raw[(long long)b * SS * KK + tid * KK + k], acc[k]);
    }
}

__global__ __launch_bounds__(128) void spatial_bn(
    const float* __restrict__ raw, const float* __restrict__ b_conv,
    const float* __restrict__ g_sp, const float* __restrict__ b_sp,
    float* __restrict__ out)
{
    const int b = blockIdx.x;
    const int tid = threadIdx.x;
    if (tid < SS) {
        float gs = g_sp[tid] * rsqrtf(1.f + 1e-5f);
        float bs = b_sp[tid];
#pragma unroll
        for (int k = 0; k < KK; k++) {
            long long idx = (long long)b * SS * KK + tid * KK + k;
            out[idx] = (raw[idx] + b_conv[k]) * gs + bs;
        }
    }
}

// ---------------- DCT pooling ----------------
__global__ __launch_bounds__(128) void dct_pool(
    const float* __restrict__ f, const float* __restrict__ dct, float* __restrict__ y)
{
    const int b = blockIdx.y;
    const int c = blockIdx.x * 4 + (threadIdx.x >> 5);
    const int lane = threadIdx.x & 31;
    const float* fb = f + ((long long)b * CCH + c) * SS;
    const float* dc = dct + (long long)c * SS;
    float s = 0.f;
    for (int p = lane; p < SS; p += 32) s = fmaf(fb[p], dc[p], s);
#pragma unroll
    for (int o = 16; o > 0; o >>= 1) s += __shfl_xor_sync(0xffffffffu, s, o);
    if (lane == 0) y[(long long)b * CCH + c] = s;
}

// ---------------- channel-attention MLP ----------------
__global__ __launch_bounds__(256) void mlp_k(
    const float* __restrict__ y, const float* __restrict__ fc1,
    const float* __restrict__ fc2, const float* __restrict__ g_ch,
    const float* __restrict__ b_ch, float* __restrict__ ck)
{
    __shared__ float ys[CCH];
    __shared__ float hs[CR];
    const int b = blockIdx.x;
    const int tid = threadIdx.x;
    for (int i = tid; i < CCH; i += 256) ys[i] = y[(long long)b * CCH + i];
    __syncthreads();
    if (tid < CR) {
        const float* r = fc1 + tid * CCH;
        float s = 0.f;
        for (int c = 0; c < CCH; c++) s = fmaf(ys[c], r[c], s);
        hs[tid] = fmaxf(s, 0.f);
    }
    __syncthreads();
    const float rs = rsqrtf(1.f + 1e-5f);
    for (int m = tid; m < CCH * KK; m += 256) {
        const float* r = fc2 + m * CR;
        float s = 0.f;
#pragma unroll
        for (int j = 0; j < CR; j++) s = fmaf(hs[j], r[j], s);
        s = 1.f / (1.f + expf(-s));
        int c = m / KK;
        ck[(long long)b * CCH * KK + m] = s * g_ch[c] * rs + b_ch[c];
    }
}

// ---------------- task kernel writer ----------------
__global__ __launch_bounds__(128) void tk_writer(
    const float* __restrict__ skt, const float* __restrict__ ckt, float* __restrict__ tk)
{
    const int c = blockIdx.x;
    for (int i = threadIdx.x; i < SS * KK; i += 128) {
        int kk = i % KK;
        tk[(long long)c * SS * KK + i] = skt[i] * ckt[c * KK + kk];
    }
}

// ---------------- final: adapted + x (8 channels per block) ----------------
__global__ __launch_bounds__(128) void final_k(
    const float* __restrict__ x, const float* __restrict__ sk,
    const float* __restrict__ ck, const float* __restrict__ tk,
    float* __restrict__ out)
{
    __shared__ float xs[13 * 13];
    __shared__ float sks[SS * KK];
    const int c0 = blockIdx.x * 8, b = blockIdx.y;
    const int tid = threadIdx.x;

    for (int i = tid; i < 169; i += 128) xs[i] = 0.f;
    for (int i = tid; i < SS * KK; i += 128) sks[i] = sk[(long long)b * SS * KK + i];
    __syncthreads();

    const int p = tid;
    const int h = p / SDIM, w = p % SDIM;

    for (int cg = 0; cg < 8; cg++) {
        const int c = c0 + cg;
        const float* xb = x + ((long long)b * CCH + c) * SS;
        if (p < SS) xs[(h + 1) * 13 + (w + 1)] = xb[p];
        __syncthreads();
        if (p < SS) {
            float ckv[KK];
#pragma unroll
            for (int k = 0; k < KK; k++) ckv[k] = ck[((long long)b * CCH + c) * KK + k];
            const float* tkc = tk + (long long)c * SS * KK;
            float acc = 0.f;
#pragma unroll
            for (int k = 0; k < KK; k++) {
                int ki = k / 3, kj = k % 3;
                float xv = xs[(h + ki) * 13 + (w + kj)];
                acc = fmaf(xv, tkc[p * KK + k] * sks[p * KK + k] * ckv[k], acc);
            }
            out[((long long)b * CCH + c) * SS + p] = acc * (1.f / 9.f) + xb[p];
        }
        __syncthreads();
    }
}

// ---------------- launch ----------------
extern "C" void kernel_launch(void* const* d_in, const int* in_sizes, int n_in,
                              void* d_out, int out_size)
{
    const float* x      = (const float*)d_in[0];
    const float* dct_w  = (const float*)d_in[1];
    const float* w_conv = (const float*)d_in[2];
    const float* b_conv = (const float*)d_in[3];
    const float* g_sp   = (const float*)d_in[4];
    const float* b_sp   = (const float*)d_in[5];
    const float* g_ch   = (const float*)d_in[6];
    const float* b_ch   = (const float*)d_in[7];
    const float* fc1    = (const float*)d_in[8];
    const float* fc2    = (const float*)d_in[9];
    const float* up_w1  = (const float*)d_in[10];
    const float* up_b1  = (const float*)d_in[11];
    const float* up_g1  = (const float*)d_in[12];
    const float* up_bb1 = (const float*)d_in[13];
    const float* up_w2  = (const float*)d_in[14];
    const float* up_b2  = (const float*)d_in[15];
    const float* up_g2  = (const float*)d_in[16];
    const float* up_bb2 = (const float*)d_in[17];
    const float* lo_w1  = (const float*)d_in[18];
    const float* lo_b1  = (const float*)d_in[19];
    const float* lo_g1  = (const float*)d_in[20];
    const float* lo_bb1 = (const float*)d_in[21];
    const float* lo_w2  = (const float*)d_in[22];
    const float* lo_b2  = (const float*)d_in[23];
    const float* lo_g2  = (const float*)d_in[24];
    const float* lo_bb2 = (const float*)d_in[25];

    float *A1, *asum, *acc1, *acc2, *tmp, *task;
    float *sk, *skraw, *skt, *sktraw, *y, *yt, *ck, *ckt;
    cudaGetSymbolAddress((void**)&A1,     g_A1);
    cudaGetSymbolAddress((void**)&asum,   g_asum);
    cudaGetSymbolAddress((void**)&acc1,   g_acc1);
    cudaGetSymbolAddress((void**)&acc2,   g_acc2);
    cudaGetSymbolAddress((void**)&tmp,    g_tmp);
    cudaGetSymbolAddress((void**)&task,   g_task);
    cudaGetSymbolAddress((void**)&sk,     g_sk);
    cudaGetSymbolAddress((void**)&skraw,  g_skraw);
    cudaGetSymbolAddress((void**)&skt,    g_skt);
    cudaGetSymbolAddress((void**)&sktraw, g_sktraw);
    cudaGetSymbolAddress((void**)&y,      g_y);
    cudaGetSymbolAddress((void**)&yt,     g_yt);
    cudaGetSymbolAddress((void**)&ck,     g_ck);
    cudaGetSymbolAddress((void**)&ckt,    g_ckt);

    float* out = (float*)d_out;
    float* tk  = out + OUT0;

    // zero all accumulators in one launch
    {
        int n0 = C2 * SS, n1 = C2 * SS, n2 = CCH * SS;
        int n3 = BATCH * SS * KK, n4 = SS * KK;
        int ntot = n0 + n1 + n2 + n3 + n4;
        zero_multi<<<(ntot + 255) / 256, 256>>>(asum, n0, acc1, n1, acc2, n2,
                                                skraw, n3, sktraw, n4);
    }

    // instance-path small kernels
    spatial_part<<<dim3(BATCH, CCH / 128), 128>>>(x, w_conv, skraw);
    spatial_bn<<<BATCH, 128>>>(skraw, b_conv, g_sp, b_sp, sk);
    dct_pool<<<dim3(CCH / 4, BATCH), 128>>>(x, dct_w, y);
    mlp_k<<<BATCH, 256>>>(y, fc1, fc2, g_ch, b_ch, ck);

    // CLM task path (tensor-core GEMMs, 3xBF16)
    tgemm<<<dim3(1, C2 / BM, BATCH), 256>>>(up_w1, x, up_b1, up_g1, up_bb1,
        A1, CCH, SS, CCH, (long long)CCH * SS, (long long)C2 * SS, 0);
    tgemm<<<dim3(1, C2 / BM, BATCH), 256>>>(up_w2, A1, up_b2, up_g2, up_bb2,
        asum, C2, SS, C2, (long long)C2 * SS, 0, 1);
    tgemm<<<dim3(16, C2 / BM, 1), 256>>>(lo_w1, asum, lo_b1, lo_g1, lo_bb1,
        acc1, C2, SS, C2 / 16, 0, 0, 3);
    epi_bn<<<(C2 * SS + 255) / 256, 256>>>(acc1, lo_b1, lo_g1, lo_bb1, tmp, SS, C2 * SS, 0);
    tgemm<<<dim3(16, CCH / BM, 1), 256>>>(lo_w2, tmp, lo_b2, lo_g2, lo_bb2,
        acc2, C2, SS, C2 / 16, 0, 0, 3);
    epi_bn<<<(CCH * SS + 255) / 256, 256>>>(acc2, lo_b2, lo_g2, lo_bb2, task, SS, CCH * SS, 1);

    // task-path small kernels
    spatial_part<<<dim3(1, CCH / 128), 128>>>(task, w_conv, sktraw);
    spatial_bn<<<1, 128>>>(sktraw, b_conv, g_sp, b_sp, skt);
    dct_pool<<<dim3(CCH / 4, 1), 128>>>(task, dct_w, yt);
    mlp_k<<<1, 256>>>(yt, fc1, fc2, g_ch, b_ch, ckt);

    // outputs
    tk_writer<<<CCH, 128>>>(skt, ckt, tk);
    final_k<<<dim3(CCH / 8, BATCH), 128>>>(x, sk, ck, tk, out);
}